// round 3
// baseline (speedup 1.0000x reference)
#include <cuda_runtime.h>
#include <cstdint>
#include <math.h>

#define NN      4096
#define HDIM    256
#define HEADS   4
#define HD      64
#define EC      131072
#define TOPK    15
#define MAINT   128   // threads in main kernel

// ---------------- device scratch (no allocation allowed) ----------------
__device__ double g_vdst[HEADS][HDIM];
__device__ double g_vsrc[HEADS][HDIM];
__device__ float4 g_sd[NN];
__device__ float4 g_ss[NN];
__device__ __align__(16) int g_cnt[NN];
__device__ int g_off[NN + 1];
__device__ int g_cur[NN];
__device__ int g_ecol[EC];
__device__ int g_epos[EC];
__device__ float g_ew[EC];
__device__ int g_mask_is_byte;   // 1 = bool arrays are 1 byte/elem, 0 = 4 bytes/elem

// ---------------- kernel 0: detect bool element width from bit signature ----------
__global__ void detect_kernel(const unsigned* __restrict__ mask_words) {
    // uint8-packed bool words: all bytes in {0,1}, and (with ~95% true density)
    // most words are 0x01010101 (> 1). int32 bools: words in {0,1}.
    // float32 bools: words in {0, 0x3F800000} (byte 0x3F > 1 -> not u8 signature).
    __shared__ int s_byte;
    if (threadIdx.x == 0) s_byte = 0;
    __syncthreads();
    for (int t = threadIdx.x; t < 4096; t += blockDim.x) {
        unsigned w = mask_words[t];
        if (w > 1u) {
            // check all bytes <= 1
            unsigned b0 = w & 0xFF, b1 = (w >> 8) & 0xFF, b2 = (w >> 16) & 0xFF, b3 = w >> 24;
            if (b0 <= 1u && b1 <= 1u && b2 <= 1u && b3 <= 1u) s_byte = 1;
        }
    }
    __syncthreads();
    if (threadIdx.x == 0) g_mask_is_byte = s_byte;
}

// ---------------- kernel 1: fold att into W  (v[h][k] = sum_d att[h][d]*W[h*64+d][k]) --
__global__ void prep_v_kernel(const float* __restrict__ W, const float* __restrict__ att) {
    int k = threadIdx.x;  // 256
    #pragma unroll
    for (int h = 0; h < HEADS; h++) {
        double d = 0.0, s = 0.0;
        #pragma unroll 8
        for (int dd = 0; dd < HD; dd++) {
            double w = (double)W[(h * HD + dd) * HDIM + k];
            d += (double)att[h * 2 * HD + dd] * w;
            s += (double)att[h * 2 * HD + HD + dd] * w;
        }
        g_vdst[h][k] = d;
        g_vsrc[h][k] = s;
    }
}

// ---------------- kernel 2: sd[n][h], ss[n][h] = E[n,:] . v[h,:]  (warp per row) ----
__global__ void sds_kernel(const float* __restrict__ E) {
    int gw = (blockIdx.x * blockDim.x + threadIdx.x) >> 5;
    int lane = threadIdx.x & 31;
    if (gw >= NN) return;
    const float* er = E + (size_t)gw * HDIM;
    double ad[HEADS] = {0, 0, 0, 0};
    double as[HEADS] = {0, 0, 0, 0};
    for (int k = lane; k < HDIM; k += 32) {
        double e = (double)er[k];
        #pragma unroll
        for (int h = 0; h < HEADS; h++) {
            ad[h] += e * g_vdst[h][k];
            as[h] += e * g_vsrc[h][k];
        }
    }
    #pragma unroll
    for (int off = 16; off; off >>= 1) {
        #pragma unroll
        for (int h = 0; h < HEADS; h++) {
            ad[h] += __shfl_down_sync(0xffffffffu, ad[h], off);
            as[h] += __shfl_down_sync(0xffffffffu, as[h], off);
        }
    }
    if (lane == 0) {
        g_sd[gw] = make_float4((float)ad[0], (float)ad[1], (float)ad[2], (float)ad[3]);
        g_ss[gw] = make_float4((float)as[0], (float)as[1], (float)as[2], (float)as[3]);
    }
}

// ---------------- CSR build for corr edges ----------------
__global__ void zero_cnt_kernel() {
    int i = blockIdx.x * blockDim.x + threadIdx.x;
    if (i < NN) g_cnt[i] = 0;
}

__global__ void count_kernel(const int* __restrict__ eidx) {
    int e = blockIdx.x * blockDim.x + threadIdx.x;
    if (e < EC) atomicAdd(&g_cnt[eidx[e]], 1);
}

__global__ void scan_kernel() {
    __shared__ int partial[1024];
    int tid = threadIdx.x;  // 1024
    int base = tid * 4;
    int4 c = *(const int4*)&g_cnt[base];
    int a0 = c.x;
    int a1 = a0 + c.y;
    int a2 = a1 + c.z;
    int a3 = a2 + c.w;
    partial[tid] = a3;
    __syncthreads();
    for (int off = 1; off < 1024; off <<= 1) {
        int v = partial[tid];
        int add = (tid >= off) ? partial[tid - off] : 0;
        __syncthreads();
        partial[tid] = v + add;
        __syncthreads();
    }
    int pre = (tid == 0) ? 0 : partial[tid - 1];
    g_off[base + 0] = pre;
    g_off[base + 1] = pre + a0;
    g_off[base + 2] = pre + a1;
    g_off[base + 3] = pre + a2;
    g_cur[base + 0] = pre;
    g_cur[base + 1] = pre + a0;
    g_cur[base + 2] = pre + a1;
    g_cur[base + 3] = pre + a2;
    if (tid == 1023) g_off[NN] = pre + a3;
}

__global__ void scatter_kernel(const int* __restrict__ eidx, const float* __restrict__ ew) {
    int e = blockIdx.x * blockDim.x + threadIdx.x;
    if (e >= EC) return;
    int r = eidx[e];
    int c = eidx[EC + e];
    int p = atomicAdd(&g_cur[r], 1);
    g_ecol[p] = c;
    g_epos[p] = e;
    g_ew[p] = ew[e];
}

// ---------------- main kernel: one row per block, fused scores + topk + softmax ----
__global__ __launch_bounds__(MAINT) void row_topk_kernel(
    const uint8_t* __restrict__ mask,
    const uint8_t* __restrict__ act,
    const float* __restrict__ lambda_p,
    float* __restrict__ out)
{
    __shared__ unsigned long long corr[NN];          // 32 KB: last-wins corr per column
    __shared__ unsigned long long pool[MAINT * TOPK]; // 15 KB: merge pool
    __shared__ unsigned long long wm[MAINT / 32];
    __shared__ int wmi[MAINT / 32];
    __shared__ unsigned long long sel[TOPK];
    __shared__ float s_ex[TOPK];

    const int i = blockIdx.x;
    const int tid = threadIdx.x;
    const int lane = tid & 31;
    const int wid = tid >> 5;
    const int is_byte = g_mask_is_byte;

    // zero corr table
    for (int j = tid; j < NN; j += MAINT) corr[j] = 0ULL;
    __syncthreads();

    // scatter this row's edges, last-wins by max original edge position
    const int beg = g_off[i], end = g_off[i + 1];
    for (int t = beg + tid; t < end; t += MAINT) {
        unsigned long long key =
            ((unsigned long long)(unsigned)g_epos[t] << 32) |
            (unsigned long long)__float_as_uint(g_ew[t]);
        atomicMax(&corr[g_ecol[t]], key);
    }
    __syncthreads();

    const float4 sdi = g_sd[i];
    const float lam = __ldg(lambda_p);
    bool acti;
    const uint8_t* mrow8 = mask + (size_t)i * NN;
    const unsigned* mrow32 = (const unsigned*)mask + (size_t)i * NN;
    const unsigned* act32 = (const unsigned*)act;
    if (is_byte) acti = act[i] != 0;
    else         acti = act32[i] != 0u;

    // per-thread sorted top-15 (descending keys)
    unsigned long long best[TOPK];
    #pragma unroll
    for (int r = 0; r < TOPK; r++) best[r] = 0ULL;

    for (int j = tid; j < NN; j += MAINT) {
        float4 ssj = __ldg(&g_ss[j]);
        float x0 = sdi.x + ssj.x;
        float x1 = sdi.y + ssj.y;
        float x2 = sdi.z + ssj.z;
        float x3 = sdi.w + ssj.w;
        // leaky_relu(x, 0.2) == max(x, 0.2x)
        x0 = fmaxf(x0, 0.2f * x0);
        x1 = fmaxf(x1, 0.2f * x1);
        x2 = fmaxf(x2, 0.2f * x2);
        x3 = fmaxf(x3, 0.2f * x3);
        float sc = (x0 + x1 + x2 + x3) * 0.25f;

        bool mj, aj;
        if (is_byte) { mj = mrow8[j] != 0;  aj = act[j] != 0; }
        else         { mj = mrow32[j] != 0u; aj = act32[j] != 0u; }

        if (acti && mj && aj) {
            unsigned long long ck = corr[j];
            if (ck) sc += lam * __uint_as_float((unsigned)ck);
        } else {
            sc = -INFINITY;
        }

        // order-preserving float->uint; tie-break: smaller j wins (larger low word)
        unsigned u = __float_as_uint(sc);
        u = (u & 0x80000000u) ? ~u : (u | 0x80000000u);
        unsigned long long key =
            ((unsigned long long)u << 32) | (unsigned long long)(0xFFFFFFFFu - (unsigned)j);

        if (key > best[TOPK - 1]) {
            int p = TOPK - 1;
            while (p > 0 && key > best[p - 1]) {
                best[p] = best[p - 1];
                --p;
            }
            best[p] = key;
        }
    }

    #pragma unroll
    for (int r = 0; r < TOPK; r++) pool[tid * TOPK + r] = best[r];
    __syncthreads();

    // iterative block-wide argmax selection, 15 rounds
    for (int it = 0; it < TOPK; it++) {
        unsigned long long m = 0ULL;
        int mi = -1;
        for (int s = tid; s < MAINT * TOPK; s += MAINT) {
            unsigned long long v = pool[s];
            if (v > m) { m = v; mi = s; }
        }
        #pragma unroll
        for (int off = 16; off; off >>= 1) {
            unsigned long long om = __shfl_down_sync(0xffffffffu, m, off);
            int omi = __shfl_down_sync(0xffffffffu, mi, off);
            if (om > m) { m = om; mi = omi; }
        }
        if (lane == 0) { wm[wid] = m; wmi[wid] = mi; }
        __syncthreads();
        if (tid == 0) {
            unsigned long long bm = wm[0];
            int bi = wmi[0];
            #pragma unroll
            for (int w = 1; w < MAINT / 32; w++)
                if (wm[w] > bm) { bm = wm[w]; bi = wmi[w]; }
            sel[it] = bm;
            pool[bi] = 0ULL;
        }
        __syncthreads();
    }

    // decode + softmax + write outputs
    if (tid < TOPK) {
        unsigned long long key = sel[tid];
        unsigned u = (unsigned)(key >> 32);
        float v = (u & 0x80000000u) ? __uint_as_float(u ^ 0x80000000u)
                                    : __uint_as_float(~u);
        unsigned j = 0xFFFFFFFFu - (unsigned)(key & 0xFFFFFFFFu);

        unsigned u0 = (unsigned)(sel[0] >> 32);
        float v0 = (u0 & 0x80000000u) ? __uint_as_float(u0 ^ 0x80000000u)
                                      : __uint_as_float(~u0);
        s_ex[tid] = expf(v - v0);

        out[(size_t)i * TOPK + tid] = (float)j;                       // edge_index[0]
        out[(size_t)NN * TOPK + (size_t)i * TOPK + tid] = (float)i;   // edge_index[1]
    }
    __syncthreads();
    if (tid < TOPK) {
        float sum = 0.f;
        #pragma unroll
        for (int r = 0; r < TOPK; r++) sum += s_ex[r];
        out[2 * (size_t)NN * TOPK + (size_t)i * TOPK + tid] = s_ex[tid] / sum;
    }
}

// ---------------- launcher ----------------
extern "C" void kernel_launch(void* const* d_in, const int* in_sizes, int n_in,
                              void* d_out, int out_size) {
    const float*   emb  = (const float*)d_in[0];    // (4096, 256)
    const float*   W    = (const float*)d_in[1];    // (256, 256)
    const float*   att  = (const float*)d_in[2];    // (4, 128)
    const float*   lam  = (const float*)d_in[3];    // (1,)
    const uint8_t* mask = (const uint8_t*)d_in[4];  // (4096, 4096) bool (elem width detected)
    const uint8_t* act  = (const uint8_t*)d_in[5];  // (4096,) bool
    const int*     eidx = (const int*)d_in[6];      // (2, 131072)
    const float*   ew   = (const float*)d_in[7];    // (131072,)
    float* out = (float*)d_out;                     // 184320 floats

    detect_kernel<<<1, 256>>>((const unsigned*)mask);
    prep_v_kernel<<<1, HDIM>>>(W, att);
    sds_kernel<<<(NN * 32 + 255) / 256, 256>>>(emb);
    zero_cnt_kernel<<<(NN + 255) / 256, 256>>>();
    count_kernel<<<EC / 256, 256>>>(eidx);
    scan_kernel<<<1, 1024>>>();
    scatter_kernel<<<EC / 256, 256>>>(eidx, ew);
    row_topk_kernel<<<NN, MAINT>>>(mask, act, lam, out);
}

// round 4
// speedup vs baseline: 4.5788x; 4.5788x over previous
#include <cuda_runtime.h>
#include <cstdint>
#include <math.h>

#define NN     4096
#define HDIM   256
#define HEADS  4
#define HD     64
#define EC     131072
#define TOPK   15
#define CAP    160      // per-row edge bucket capacity (Poisson(32); 160 is unreachable)
#define RT     512      // row-kernel threads
#define CPT    8        // candidates per thread = NN / RT

// ---------------- device scratch ----------------
__device__ float2 g_vd[HEADS][HDIM];   // folded att_dst . W  (hi, lo)
__device__ float2 g_vs[HEADS][HDIM];   // folded att_src . W  (hi, lo)
__device__ float4 g_sd[NN];
__device__ float4 g_ss[NN];
__device__ int    g_cur[NN];
__device__ int    g_ecol[NN * CAP];
__device__ int    g_epos[NN * CAP];
__device__ float  g_ew[NN * CAP];
__device__ int    g_is_byte;

// ---------------- double-single helpers ----------------
__device__ __forceinline__ void dsadd(float& s, float& c, float p, float pe) {
    // TwoSum(s, p) then fold error + product-error into compensation c
    float t = s + p;
    float z = t - s;
    float e = (s - (t - z)) + (p - z);
    s = t;
    c += e + pe;
}

// ---------------- L1: detect bool width + fold att into W + zero buckets ------
__global__ void k_setup(const unsigned* __restrict__ mask_words,
                        const float* __restrict__ W,
                        const float* __restrict__ att) {
    int b = blockIdx.x, tid = threadIdx.x;
    if (b == 0) {
        // detect bool element width from bit signature of first 4096 words
        __shared__ int s_byte;
        if (tid == 0) s_byte = 0;
        __syncthreads();
        for (int t = tid; t < 4096; t += blockDim.x) {
            unsigned w = mask_words[t];
            if (w > 1u) {
                unsigned b0 = w & 0xFF, b1 = (w >> 8) & 0xFF,
                         b2 = (w >> 16) & 0xFF, b3 = w >> 24;
                if (b0 <= 1u && b1 <= 1u && b2 <= 1u && b3 <= 1u) s_byte = 1;
            }
        }
        __syncthreads();
        if (tid == 0) g_is_byte = s_byte;
    } else if (b == 1) {
        // v[h][k] = sum_d att[h][d] * W[h*64+d][k]   (double-single fp32)
        int k = tid;  // 256 threads == HDIM
        #pragma unroll
        for (int h = 0; h < HEADS; h++) {
            float sd = 0.f, cd = 0.f, ss = 0.f, cs = 0.f;
            for (int dd = 0; dd < HD; dd++) {
                float w  = W[(h * HD + dd) * HDIM + k];
                float ad = att[h * 2 * HD + dd];
                float as_ = att[h * 2 * HD + HD + dd];
                float p  = ad * w;  float pe = fmaf(ad, w, -p);
                dsadd(sd, cd, p, pe);
                p = as_ * w;        pe = fmaf(as_, w, -p);
                dsadd(ss, cs, p, pe);
            }
            float hi = sd + cd;  float lo = (sd - hi) + cd;
            g_vd[h][k] = make_float2(hi, lo);
            hi = ss + cs;        lo = (ss - hi) + cs;
            g_vs[h][k] = make_float2(hi, lo);
        }
    } else {
        int i = (b - 2) * 256 + tid;   // blocks 2..17 zero 4096 counters
        if (i < NN) g_cur[i] = 0;
    }
}

// ---------------- L2: sds (blocks 0..127) + edge scatter (blocks 128..255) ----
__global__ __launch_bounds__(1024) void k_mid(const float* __restrict__ E,
                                              const int* __restrict__ eidx,
                                              const float* __restrict__ ew) {
    int b = blockIdx.x;
    if (b < 128) {
        // one warp per row: sd[n][h], ss[n][h] = E[n,:] . v[h,:]  (double-single)
        int wid = threadIdx.x >> 5;
        int lane = threadIdx.x & 31;
        int g = b * 32 + wid;                 // 128*32 = 4096 rows
        const float* er = E + (size_t)g * HDIM;
        float s[8], c[8];
        #pragma unroll
        for (int a = 0; a < 8; a++) { s[a] = 0.f; c[a] = 0.f; }
        for (int k = lane; k < HDIM; k += 32) {
            float e = er[k];
            #pragma unroll
            for (int h = 0; h < HEADS; h++) {
                float2 v = g_vd[h][k];
                float p = e * v.x;
                float pe = fmaf(e, v.x, -p);
                pe = fmaf(e, v.y, pe);
                dsadd(s[h], c[h], p, pe);
                v = g_vs[h][k];
                p = e * v.x;
                pe = fmaf(e, v.x, -p);
                pe = fmaf(e, v.y, pe);
                dsadd(s[4 + h], c[4 + h], p, pe);
            }
        }
        #pragma unroll
        for (int off = 16; off; off >>= 1) {
            #pragma unroll
            for (int a = 0; a < 8; a++) {
                float os = __shfl_down_sync(0xffffffffu, s[a], off);
                float oc = __shfl_down_sync(0xffffffffu, c[a], off);
                float t = s[a] + os;
                float z = t - s[a];
                float e2 = (s[a] - (t - z)) + (os - z);
                s[a] = t;
                c[a] += oc + e2;
            }
        }
        if (lane == 0) {
            g_sd[g] = make_float4(s[0] + c[0], s[1] + c[1], s[2] + c[2], s[3] + c[3]);
            g_ss[g] = make_float4(s[4] + c[4], s[5] + c[5], s[6] + c[6], s[7] + c[7]);
        }
    } else {
        int e = (b - 128) * 1024 + threadIdx.x;   // 128*1024 = 131072 edges
        if (e < EC) {
            int r = eidx[e];
            int cc = eidx[EC + e];
            int p = atomicAdd(&g_cur[r], 1);
            if (p < CAP) {
                g_ecol[r * CAP + p] = cc;
                g_epos[r * CAP + p] = e;
                g_ew[r * CAP + p]   = ew[e];
            }
        }
    }
}

// ---------------- L3: one row per block, fused scores + top-15 + softmax ------
__global__ __launch_bounds__(RT) void k_row(const uint8_t* __restrict__ mask,
                                            const uint8_t* __restrict__ act,
                                            const float* __restrict__ lambda_p,
                                            float* __restrict__ out) {
    __shared__ unsigned long long corr[NN];      // 32 KB: last-wins corr per column
    __shared__ unsigned long long wmax[RT / 32];
    __shared__ int wwho[RT / 32];
    __shared__ unsigned long long s_sel[TOPK];
    __shared__ float s_ex[TOPK];
    __shared__ int s_winner;

    const int i = blockIdx.x;
    const int tid = threadIdx.x;
    const int lane = tid & 31;
    const int wid = tid >> 5;

    // zero corr table
    #pragma unroll
    for (int k = 0; k < NN / RT; k++) corr[tid + k * RT] = 0ULL;
    __syncthreads();

    // scatter this row's edges, last-wins via max original edge position
    int cnt = g_cur[i];
    if (cnt > CAP) cnt = CAP;
    for (int t = tid; t < cnt; t += RT) {
        unsigned long long key =
            ((unsigned long long)(unsigned)g_epos[i * CAP + t] << 32) |
            (unsigned long long)__float_as_uint(g_ew[i * CAP + t]);
        atomicMax(&corr[g_ecol[i * CAP + t]], key);
    }
    __syncthreads();

    const float4 sdi = g_sd[i];
    const float lam = __ldg(lambda_p);
    const int is_byte = g_is_byte;
    const uint8_t*  mrow8  = mask + (size_t)i * NN;
    const unsigned* mrow32 = (const unsigned*)mask + (size_t)i * NN;
    const unsigned* act32  = (const unsigned*)act;
    const bool acti = is_byte ? (act[i] != 0) : (act32[i] != 0u);

    // ---- compute 8 candidate keys into registers ----
    unsigned long long key[CPT];
    #pragma unroll
    for (int k = 0; k < CPT; k++) {
        int j = tid + k * RT;
        float4 ssj = __ldg(&g_ss[j]);
        float x0 = sdi.x + ssj.x;
        float x1 = sdi.y + ssj.y;
        float x2 = sdi.z + ssj.z;
        float x3 = sdi.w + ssj.w;
        x0 = fmaxf(x0, 0.2f * x0);
        x1 = fmaxf(x1, 0.2f * x1);
        x2 = fmaxf(x2, 0.2f * x2);
        x3 = fmaxf(x3, 0.2f * x3);
        float sc = (x0 + x1 + x2 + x3) * 0.25f;

        bool mj, aj;
        if (is_byte) { mj = mrow8[j] != 0;  aj = act[j] != 0; }
        else         { mj = mrow32[j] != 0u; aj = act32[j] != 0u; }

        if (acti && mj && aj) {
            unsigned long long ck = corr[j];
            if (ck) sc += lam * __uint_as_float((unsigned)ck);
        } else {
            sc = -INFINITY;
        }
        unsigned u = __float_as_uint(sc);
        u = (u & 0x80000000u) ? ~u : (u | 0x80000000u);
        key[k] = ((unsigned long long)u << 32) |
                 (unsigned long long)(0xFFFFFFFFu - (unsigned)j);
    }

    // ---- sort the 8 keys descending: Batcher odd-even mergesort (19 CE) ----
#define CE(a, b) { unsigned long long _x = key[a], _y = key[b]; \
                   key[a] = (_x > _y) ? _x : _y; key[b] = (_x > _y) ? _y : _x; }
    CE(0,1) CE(2,3) CE(0,2) CE(1,3) CE(1,2)      // sort 0..3
    CE(4,5) CE(6,7) CE(4,6) CE(5,7) CE(5,6)      // sort 4..7
    CE(0,4) CE(1,5) CE(2,6) CE(3,7)              // merge
    CE(2,4) CE(3,5)
    CE(1,2) CE(3,4) CE(5,6)
#undef CE

    // ---- 15 rounds of block-argmax over register heads ----
    for (int it = 0; it < TOPK; it++) {
        unsigned long long m = key[0];
        int who = tid;
        #pragma unroll
        for (int off = 16; off; off >>= 1) {
            unsigned long long om = __shfl_down_sync(0xffffffffu, m, off);
            int ow = __shfl_down_sync(0xffffffffu, who, off);
            if (om > m) { m = om; who = ow; }
        }
        if (lane == 0) { wmax[wid] = m; wwho[wid] = who; }
        __syncthreads();
        if (wid == 0) {
            unsigned long long m2 = (lane < RT / 32) ? wmax[lane] : 0ULL;
            int w2 = (lane < RT / 32) ? wwho[lane] : 0;
            #pragma unroll
            for (int off = 8; off; off >>= 1) {
                unsigned long long om = __shfl_down_sync(0xffffffffu, m2, off);
                int ow = __shfl_down_sync(0xffffffffu, w2, off);
                if (om > m2) { m2 = om; w2 = ow; }
            }
            if (lane == 0) { s_sel[it] = m2; s_winner = w2; }
        }
        __syncthreads();
        if (tid == s_winner) {
            #pragma unroll
            for (int r = 0; r < CPT - 1; r++) key[r] = key[r + 1];
            key[CPT - 1] = 0ULL;
        }
    }

    // ---- decode + softmax + write outputs ----
    if (tid < TOPK) {
        unsigned long long k64 = s_sel[tid];
        unsigned u = (unsigned)(k64 >> 32);
        float v = (u & 0x80000000u) ? __uint_as_float(u ^ 0x80000000u)
                                    : __uint_as_float(~u);
        unsigned j = 0xFFFFFFFFu - (unsigned)(k64 & 0xFFFFFFFFu);

        unsigned u0 = (unsigned)(s_sel[0] >> 32);
        float v0 = (u0 & 0x80000000u) ? __uint_as_float(u0 ^ 0x80000000u)
                                      : __uint_as_float(~u0);
        s_ex[tid] = expf(v - v0);

        out[(size_t)i * TOPK + tid] = (float)j;                        // edge_index[0]
        out[(size_t)NN * TOPK + (size_t)i * TOPK + tid] = (float)i;    // edge_index[1]
    }
    __syncthreads();
    if (tid < TOPK) {
        float sum = 0.f;
        #pragma unroll
        for (int r = 0; r < TOPK; r++) sum += s_ex[r];
        out[2 * (size_t)NN * TOPK + (size_t)i * TOPK + tid] = s_ex[tid] / sum;
    }
}

// ---------------- launcher: 3 kernels ----------------
extern "C" void kernel_launch(void* const* d_in, const int* in_sizes, int n_in,
                              void* d_out, int out_size) {
    const float*   emb  = (const float*)d_in[0];    // (4096, 256)
    const float*   W    = (const float*)d_in[1];    // (256, 256)
    const float*   att  = (const float*)d_in[2];    // (4, 128)
    const float*   lam  = (const float*)d_in[3];    // (1,)
    const uint8_t* mask = (const uint8_t*)d_in[4];  // (4096, 4096) bool
    const uint8_t* act  = (const uint8_t*)d_in[5];  // (4096,) bool
    const int*     eidx = (const int*)d_in[6];      // (2, 131072)
    const float*   ew   = (const float*)d_in[7];    // (131072,)
    float* out = (float*)d_out;

    k_setup<<<18, 256>>>((const unsigned*)mask, W, att);
    k_mid<<<256, 1024>>>(emb, eidx, ew);
    k_row<<<NN, RT>>>(mask, act, lam, out);
}

// round 5
// speedup vs baseline: 6.1692x; 1.3473x over previous
#include <cuda_runtime.h>
#include <cstdint>
#include <math.h>

#define NN     4096
#define HDIM   256
#define HEADS  4
#define HD     64
#define EC     131072
#define TOPK   15
#define CAP    160      // per-row edge bucket capacity (Poisson(32); 160 unreachable)
#define RT     512      // row-kernel threads
#define CPT    8        // candidates per thread = NN / RT
#define FULLM  0xffffffffu

// ---------------- device scratch ----------------
__device__ float2 g_vd[HEADS][HDIM];   // folded att_dst . W  (hi, lo)
__device__ float2 g_vs[HEADS][HDIM];   // folded att_src . W  (hi, lo)
__device__ float4 g_sd[NN];
__device__ float4 g_ss[NN];            // act[j]==0 rows poisoned to -inf sentinel
__device__ int    g_cur[NN];
__device__ int    g_ecol[NN * CAP];
__device__ int    g_epos[NN * CAP];
__device__ float  g_ew[NN * CAP];
__device__ int    g_is_byte;

// ---------------- double-single helpers ----------------
__device__ __forceinline__ void dsadd(float& s, float& c, float p, float pe) {
    float t = s + p;
    float z = t - s;
    float e = (s - (t - z)) + (p - z);
    s = t;
    c += e + pe;
}

// ---------------- L1: detect bool width + zero buckets + parallel fold --------
__global__ __launch_bounds__(256) void k_setup(const unsigned* __restrict__ mask_words,
                                               const float* __restrict__ W,
                                               const float* __restrict__ att) {
    int b = blockIdx.x, tid = threadIdx.x;
    if (b == 0) {
        __shared__ int s_byte;
        if (tid == 0) s_byte = 0;
        __syncthreads();
        for (int t = tid; t < 4096; t += 256) {
            unsigned w = mask_words[t];
            if (w > 1u) {
                unsigned b0 = w & 0xFF, b1 = (w >> 8) & 0xFF,
                         b2 = (w >> 16) & 0xFF, b3 = w >> 24;
                if (b0 <= 1u && b1 <= 1u && b2 <= 1u && b3 <= 1u) s_byte = 1;
            }
        }
        __syncthreads();
        if (tid == 0) g_is_byte = s_byte;
    } else if (b <= 16) {
        g_cur[(b - 1) * 256 + tid] = 0;
    } else {
        // fold: warp per (h,k).  blocks 17..144, 8 warps each = 1024 warps
        int gw = (b - 17) * 8 + (tid >> 5);     // 0..1023
        int lane = tid & 31;
        int h = gw >> 8;
        int k = gw & 255;
        float sd = 0.f, cd = 0.f, ss = 0.f, cs = 0.f;
        #pragma unroll
        for (int r = 0; r < 2; r++) {
            int dd = lane + r * 32;
            float w  = W[(h * HD + dd) * HDIM + k];
            float ad = att[h * 2 * HD + dd];
            float as_ = att[h * 2 * HD + HD + dd];
            float p = ad * w;  float pe = fmaf(ad, w, -p);
            dsadd(sd, cd, p, pe);
            p = as_ * w;       pe = fmaf(as_, w, -p);
            dsadd(ss, cs, p, pe);
        }
        #pragma unroll
        for (int off = 16; off; off >>= 1) {
            float os = __shfl_down_sync(FULLM, sd, off);
            float oc = __shfl_down_sync(FULLM, cd, off);
            float t = sd + os; float z = t - sd;
            cd += oc + ((sd - (t - z)) + (os - z)); sd = t;
            os = __shfl_down_sync(FULLM, ss, off);
            oc = __shfl_down_sync(FULLM, cs, off);
            t = ss + os; z = t - ss;
            cs += oc + ((ss - (t - z)) + (os - z)); ss = t;
        }
        if (lane == 0) {
            float hi = sd + cd;
            g_vd[h][k] = make_float2(hi, (sd - hi) + cd);
            hi = ss + cs;
            g_vs[h][k] = make_float2(hi, (ss - hi) + cs);
        }
    }
}

// ---------------- L2: sds (blocks 0..127) + edge scatter (blocks 128..255) ----
__global__ __launch_bounds__(1024) void k_mid(const float* __restrict__ E,
                                              const int* __restrict__ eidx,
                                              const float* __restrict__ ew,
                                              const uint8_t* __restrict__ act) {
    int b = blockIdx.x;
    if (b < 128) {
        int wid = threadIdx.x >> 5;
        int lane = threadIdx.x & 31;
        int g = b * 32 + wid;
        const float* er = E + (size_t)g * HDIM;
        float s[8], c[8];
        #pragma unroll
        for (int a = 0; a < 8; a++) { s[a] = 0.f; c[a] = 0.f; }
        for (int k = lane; k < HDIM; k += 32) {
            float e = er[k];
            #pragma unroll
            for (int h = 0; h < HEADS; h++) {
                float2 v = g_vd[h][k];
                float p = e * v.x;
                float pe = fmaf(e, v.x, -p);
                pe = fmaf(e, v.y, pe);
                dsadd(s[h], c[h], p, pe);
                v = g_vs[h][k];
                p = e * v.x;
                pe = fmaf(e, v.x, -p);
                pe = fmaf(e, v.y, pe);
                dsadd(s[4 + h], c[4 + h], p, pe);
            }
        }
        #pragma unroll
        for (int off = 16; off; off >>= 1) {
            #pragma unroll
            for (int a = 0; a < 8; a++) {
                float os = __shfl_down_sync(FULLM, s[a], off);
                float oc = __shfl_down_sync(FULLM, c[a], off);
                float t = s[a] + os;
                float z = t - s[a];
                c[a] += oc + ((s[a] - (t - z)) + (os - z));
                s[a] = t;
            }
        }
        if (lane == 0) {
            bool aj = g_is_byte ? (act[g] != 0) : (((const unsigned*)act)[g] != 0u);
            g_sd[g] = make_float4(s[0] + c[0], s[1] + c[1], s[2] + c[2], s[3] + c[3]);
            if (aj)
                g_ss[g] = make_float4(s[4] + c[4], s[5] + c[5], s[6] + c[6], s[7] + c[7]);
            else   // act[j]==0: poison so score becomes -inf regardless of corr
                g_ss[g] = make_float4(-INFINITY, -INFINITY, -INFINITY, -INFINITY);
        }
    } else {
        int e = (b - 128) * 1024 + threadIdx.x;
        if (e < EC) {
            int r = eidx[e];
            int cc = eidx[EC + e];
            int p = atomicAdd(&g_cur[r], 1);
            if (p < CAP) {
                g_ecol[r * CAP + p] = cc;
                g_epos[r * CAP + p] = e;
                g_ew[r * CAP + p]   = ew[e];
            }
        }
    }
}

// warp-level: 15 rounds of bfly argmax over sorted register heads; each round
// the globally-max head is popped and kept by lane==it in 'mine'.
__device__ __forceinline__ void warp_top15(unsigned long long key[CPT],
                                           int lane,
                                           unsigned long long& mine) {
    mine = 0ULL;
    #pragma unroll
    for (int it = 0; it < TOPK; it++) {
        unsigned long long m = key[0];
        #pragma unroll
        for (int off = 16; off; off >>= 1) {
            unsigned long long om = __shfl_xor_sync(FULLM, m, off);
            if (om > m) m = om;
        }
        unsigned bal = __ballot_sync(FULLM, key[0] == m);
        int who = __ffs(bal) - 1;
        if (lane == who) {
            #pragma unroll
            for (int r = 0; r < CPT - 1; r++) key[r] = key[r + 1];
            key[CPT - 1] = 0ULL;
        }
        if (lane == it) mine = m;
    }
}

// ---------------- L3: one row per block, fused scores + top-15 + softmax ------
__global__ __launch_bounds__(RT) void k_row(const uint8_t* __restrict__ mask,
                                            const uint8_t* __restrict__ act,
                                            const float* __restrict__ lambda_p,
                                            float* __restrict__ out) {
    __shared__ unsigned long long corr[NN];            // 32 KB
    __shared__ unsigned long long pool[(RT / 32) * TOPK];  // 240 keys
    __shared__ unsigned long long s_sel[TOPK];
    __shared__ float s_ex[TOPK];

    const int i = blockIdx.x;
    const int tid = threadIdx.x;
    const int lane = tid & 31;
    const int wid = tid >> 5;

    #pragma unroll
    for (int k = 0; k < NN / RT; k++) corr[tid + k * RT] = 0ULL;
    __syncthreads();

    int cnt = g_cur[i];
    if (cnt > CAP) cnt = CAP;
    for (int t = tid; t < cnt; t += RT) {
        unsigned long long key =
            ((unsigned long long)(unsigned)g_epos[i * CAP + t] << 32) |
            (unsigned long long)__float_as_uint(g_ew[i * CAP + t]);
        atomicMax(&corr[g_ecol[i * CAP + t]], key);
    }
    __syncthreads();

    const float4 sdi = g_sd[i];
    const float lam = __ldg(lambda_p);
    const int is_byte = g_is_byte;
    const uint8_t*  mrow8  = mask + (size_t)i * NN;
    const unsigned* mrow32 = (const unsigned*)mask + (size_t)i * NN;
    const bool acti = is_byte ? (act[i] != 0) : (((const unsigned*)act)[i] != 0u);

    // ---- 8 candidate keys in registers ----
    unsigned long long key[CPT];
    #pragma unroll
    for (int k = 0; k < CPT; k++) {
        int j = tid + k * RT;
        float4 ssj = __ldg(&g_ss[j]);
        float x0 = sdi.x + ssj.x;
        float x1 = sdi.y + ssj.y;
        float x2 = sdi.z + ssj.z;
        float x3 = sdi.w + ssj.w;
        x0 = fmaxf(x0, 0.2f * x0);
        x1 = fmaxf(x1, 0.2f * x1);
        x2 = fmaxf(x2, 0.2f * x2);
        x3 = fmaxf(x3, 0.2f * x3);
        float sc = (x0 + x1 + x2 + x3) * 0.25f;

        bool mj = is_byte ? (mrow8[j] != 0) : (mrow32[j] != 0u);
        if (acti && mj) {
            unsigned long long ck = corr[j];
            if (ck) sc += lam * __uint_as_float((unsigned)ck);
        } else {
            sc = -INFINITY;
        }
        unsigned u = __float_as_uint(sc);
        u = (u & 0x80000000u) ? ~u : (u | 0x80000000u);
        key[k] = ((unsigned long long)u << 32) |
                 (unsigned long long)(0xFFFFFFFFu - (unsigned)j);
    }

    // ---- sort 8 keys descending (Batcher, 19 CE) ----
#define CE(a, b) { unsigned long long _x = key[a], _y = key[b]; \
                   key[a] = (_x > _y) ? _x : _y; key[b] = (_x > _y) ? _y : _x; }
    CE(0,1) CE(2,3) CE(0,2) CE(1,3) CE(1,2)
    CE(4,5) CE(6,7) CE(4,6) CE(5,7) CE(5,6)
    CE(0,4) CE(1,5) CE(2,6) CE(3,7)
    CE(2,4) CE(3,5)
    CE(1,2) CE(3,4) CE(5,6)
#undef CE

    // ---- Phase A: per-warp top-15 (barrier-free) ----
    unsigned long long mine;
    warp_top15(key, lane, mine);
    if (lane < TOPK) pool[wid * TOPK + lane] = mine;
    __syncthreads();

    // ---- Phase B: warp 0 merges 240 survivors ----
    if (wid == 0) {
        unsigned long long k2[CPT];
        #pragma unroll
        for (int r = 0; r < CPT; r++) {
            int s = lane + r * 32;
            k2[r] = (s < (RT / 32) * TOPK) ? pool[s] : 0ULL;
        }
#define CE(a, b) { unsigned long long _x = k2[a], _y = k2[b]; \
                   k2[a] = (_x > _y) ? _x : _y; k2[b] = (_x > _y) ? _y : _x; }
        CE(0,1) CE(2,3) CE(0,2) CE(1,3) CE(1,2)
        CE(4,5) CE(6,7) CE(4,6) CE(5,7) CE(5,6)
        CE(0,4) CE(1,5) CE(2,6) CE(3,7)
        CE(2,4) CE(3,5)
        CE(1,2) CE(3,4) CE(5,6)
#undef CE
        unsigned long long fin;
        warp_top15(k2, lane, fin);
        if (lane < TOPK) s_sel[lane] = fin;
    }
    __syncthreads();

    // ---- decode + softmax + write ----
    if (tid < TOPK) {
        unsigned long long k64 = s_sel[tid];
        unsigned u = (unsigned)(k64 >> 32);
        float v = (u & 0x80000000u) ? __uint_as_float(u ^ 0x80000000u)
                                    : __uint_as_float(~u);
        unsigned j = 0xFFFFFFFFu - (unsigned)(k64 & 0xFFFFFFFFu);

        unsigned u0 = (unsigned)(s_sel[0] >> 32);
        float v0 = (u0 & 0x80000000u) ? __uint_as_float(u0 ^ 0x80000000u)
                                      : __uint_as_float(~u0);
        s_ex[tid] = expf(v - v0);

        out[(size_t)i * TOPK + tid] = (float)j;
        out[(size_t)NN * TOPK + (size_t)i * TOPK + tid] = (float)i;
    }
    __syncthreads();
    if (tid < TOPK) {
        float sum = 0.f;
        #pragma unroll
        for (int r = 0; r < TOPK; r++) sum += s_ex[r];
        out[2 * (size_t)NN * TOPK + (size_t)i * TOPK + tid] = s_ex[tid] / sum;
    }
}

// ---------------- launcher ----------------
extern "C" void kernel_launch(void* const* d_in, const int* in_sizes, int n_in,
                              void* d_out, int out_size) {
    const float*   emb  = (const float*)d_in[0];
    const float*   W    = (const float*)d_in[1];
    const float*   att  = (const float*)d_in[2];
    const float*   lam  = (const float*)d_in[3];
    const uint8_t* mask = (const uint8_t*)d_in[4];
    const uint8_t* act  = (const uint8_t*)d_in[5];
    const int*     eidx = (const int*)d_in[6];
    const float*   ew   = (const float*)d_in[7];
    float* out = (float*)d_out;

    k_setup<<<145, 256>>>((const unsigned*)mask, W, att);
    k_mid<<<256, 1024>>>(emb, eidx, ew, act);
    k_row<<<NN, RT>>>(mask, act, lam, out);
}

// round 6
// speedup vs baseline: 6.3207x; 1.0246x over previous
#include <cuda_runtime.h>
#include <cstdint>
#include <math.h>

#define NN     4096
#define HDIM   256
#define HEADS  4
#define HD     64
#define EC     131072
#define TOPK   15
#define CAP    160      // per-row edge bucket capacity (Poisson(32); unreachable)
#define RT     512      // row-kernel threads
#define CPT    8        // candidates per thread = NN / RT
#define FULLM  0xffffffffu

// ---------------- device scratch ----------------
__device__ float2 g_vd[HEADS][HDIM];   // folded att_dst . W  (hi, lo)
__device__ float2 g_vs[HEADS][HDIM];   // folded att_src . W  (hi, lo)
__device__ float4 g_sd[NN];
__device__ float4 g_ss[NN];
__device__ float  g_badj[NN];          // act_j ? 0.15*sum(ss_j) : -inf
__device__ int    g_cur[NN];
__device__ int    g_ecol[NN * CAP];
__device__ int    g_epos[NN * CAP];
__device__ float  g_ew[NN * CAP];
__device__ int    g_is_byte;

// ---------------- double-single helpers ----------------
__device__ __forceinline__ void dsadd(float& s, float& c, float p, float pe) {
    float t = s + p;
    float z = t - s;
    float e = (s - (t - z)) + (p - z);
    s = t;
    c += e + pe;
}

// ---------------- L1: detect bool width + zero buckets + fold (coalesced) -----
__global__ __launch_bounds__(256) void k_setup(const unsigned* __restrict__ mask_words,
                                               const float* __restrict__ W,
                                               const float* __restrict__ att) {
    int b = blockIdx.x, tid = threadIdx.x;
    if (b == 0) {
        __shared__ int s_byte;
        if (tid == 0) s_byte = 0;
        __syncthreads();
        for (int t = tid; t < 4096; t += 256) {
            unsigned w = mask_words[t];
            if (w > 1u) {
                unsigned b0 = w & 0xFF, b1 = (w >> 8) & 0xFF,
                         b2 = (w >> 16) & 0xFF, b3 = w >> 24;
                if (b0 <= 1u && b1 <= 1u && b2 <= 1u && b3 <= 1u) s_byte = 1;
            }
        }
        __syncthreads();
        if (tid == 0) g_is_byte = s_byte;
    } else if (b <= 16) {
        g_cur[(b - 1) * 256 + tid] = 0;
    } else {
        // fold: block per head, thread per k, coalesced over dd
        int h = b - 17;          // 0..3
        int k = tid;             // 0..255
        float sd = 0.f, cd = 0.f, ss = 0.f, cs = 0.f;
        #pragma unroll 8
        for (int dd = 0; dd < HD; dd++) {
            float w   = W[(h * HD + dd) * HDIM + k];
            float ad  = att[h * 2 * HD + dd];
            float as_ = att[h * 2 * HD + HD + dd];
            float p = ad * w;  float pe = fmaf(ad, w, -p);
            dsadd(sd, cd, p, pe);
            p = as_ * w;       pe = fmaf(as_, w, -p);
            dsadd(ss, cs, p, pe);
        }
        float hi = sd + cd;
        g_vd[h][k] = make_float2(hi, (sd - hi) + cd);
        hi = ss + cs;
        g_vs[h][k] = make_float2(hi, (ss - hi) + cs);
    }
}

// ---------------- L2: sds (blocks 0..127) + edge scatter (blocks 128..255) ----
__global__ __launch_bounds__(1024) void k_mid(const float* __restrict__ E,
                                              const int* __restrict__ eidx,
                                              const float* __restrict__ ew,
                                              const uint8_t* __restrict__ act) {
    int b = blockIdx.x;
    if (b < 128) {
        int wid = threadIdx.x >> 5;
        int lane = threadIdx.x & 31;
        int g = b * 32 + wid;
        const float* er = E + (size_t)g * HDIM;
        float s[8], c[8];
        #pragma unroll
        for (int a = 0; a < 8; a++) { s[a] = 0.f; c[a] = 0.f; }
        for (int k = lane; k < HDIM; k += 32) {
            float e = er[k];
            #pragma unroll
            for (int h = 0; h < HEADS; h++) {
                float2 v = g_vd[h][k];
                float p = e * v.x;
                float pe = fmaf(e, v.x, -p);
                pe = fmaf(e, v.y, pe);
                dsadd(s[h], c[h], p, pe);
                v = g_vs[h][k];
                p = e * v.x;
                pe = fmaf(e, v.x, -p);
                pe = fmaf(e, v.y, pe);
                dsadd(s[4 + h], c[4 + h], p, pe);
            }
        }
        #pragma unroll
        for (int off = 16; off; off >>= 1) {
            #pragma unroll
            for (int a = 0; a < 8; a++) {
                float os = __shfl_down_sync(FULLM, s[a], off);
                float oc = __shfl_down_sync(FULLM, c[a], off);
                float t = s[a] + os;
                float z = t - s[a];
                c[a] += oc + ((s[a] - (t - z)) + (os - z));
                s[a] = t;
            }
        }
        if (lane == 0) {
            g_sd[g] = make_float4(s[0] + c[0], s[1] + c[1], s[2] + c[2], s[3] + c[3]);
            float t0 = s[4] + c[4], t1 = s[5] + c[5], t2 = s[6] + c[6], t3 = s[7] + c[7];
            g_ss[g] = make_float4(t0, t1, t2, t3);
            bool aj = g_is_byte ? (act[g] != 0) : (((const unsigned*)act)[g] != 0u);
            g_badj[g] = aj ? 0.15f * ((t0 + t1) + (t2 + t3)) : -INFINITY;
        }
    } else {
        int e = (b - 128) * 1024 + threadIdx.x;
        if (e < EC) {
            int r = eidx[e];
            int cc = eidx[EC + e];
            int p = atomicAdd(&g_cur[r], 1);
            if (p < CAP) {
                g_ecol[r * CAP + p] = cc;
                g_epos[r * CAP + p] = e;
                g_ew[r * CAP + p]   = ew[e];
            }
        }
    }
}

// warp-level: 15 rounds of bfly argmax over sorted register heads
__device__ __forceinline__ void warp_top15(unsigned long long key[CPT],
                                           int lane,
                                           unsigned long long& mine) {
    mine = 0ULL;
    #pragma unroll
    for (int it = 0; it < TOPK; it++) {
        unsigned long long m = key[0];
        #pragma unroll
        for (int off = 16; off; off >>= 1) {
            unsigned long long om = __shfl_xor_sync(FULLM, m, off);
            if (om > m) m = om;
        }
        unsigned bal = __ballot_sync(FULLM, key[0] == m);
        int who = __ffs(bal) - 1;
        if (lane == who) {
            #pragma unroll
            for (int r = 0; r < CPT - 1; r++) key[r] = key[r + 1];
            key[CPT - 1] = 0ULL;
        }
        if (lane == it) mine = m;
    }
}

// ---------------- L3: one row per block ----------------
__global__ __launch_bounds__(RT) void k_row(const uint8_t* __restrict__ mask,
                                            const uint8_t* __restrict__ act,
                                            const float* __restrict__ lambda_p,
                                            float* __restrict__ out) {
    __shared__ unsigned long long corr[NN];                // 32 KB; low 16 KB reused as adj[]
    __shared__ unsigned long long pool[(RT / 32) * TOPK];
    __shared__ unsigned long long s_sel[TOPK];
    __shared__ float s_ex[TOPK];
    float* adj = (float*)corr;                             // aliased after sync

    const int i = blockIdx.x;
    const int tid = threadIdx.x;
    const int lane = tid & 31;
    const int wid = tid >> 5;

    #pragma unroll
    for (int k = 0; k < NN / RT; k++) corr[tid + k * RT] = 0ULL;
    __syncthreads();

    int cnt = g_cur[i];
    if (cnt > CAP) cnt = CAP;
    for (int t = tid; t < cnt; t += RT) {
        unsigned long long key =
            ((unsigned long long)(unsigned)g_epos[i * CAP + t] << 32) |
            (unsigned long long)__float_as_uint(g_ew[i * CAP + t]);
        atomicMax(&corr[g_ecol[i * CAP + t]], key);
    }
    __syncthreads();

    const float4 sdi = g_sd[i];
    const float ci = 0.15f * ((sdi.x + sdi.y) + (sdi.z + sdi.w));
    const float lam = __ldg(lambda_p);
    const int is_byte = g_is_byte;
    const uint8_t*  mrow8  = mask + (size_t)i * NN;
    const unsigned* mrow32 = (const unsigned*)mask + (size_t)i * NN;
    const bool acti = is_byte ? (act[i] != 0) : (((const unsigned*)act)[i] != 0u);

    // ---- pre-pass: adj[j] = mask&act ? badj_j + lam*corr_j : -inf ----
    float av[CPT];
    #pragma unroll
    for (int c = 0; c < CPT; c++) {
        int j = tid + c * RT;
        bool mj = is_byte ? (mrow8[j] != 0) : (mrow32[j] != 0u);
        float a = g_badj[j];
        unsigned long long ck = corr[j];
        if (ck) a += lam * __uint_as_float((unsigned)ck);
        av[c] = (acti && mj) ? a : -INFINITY;
    }
    __syncthreads();
    #pragma unroll
    for (int c = 0; c < CPT; c++) adj[tid + c * RT] = av[c];
    __syncthreads();

    // ---- main loop: 8 candidate keys ----
    unsigned long long key[CPT];
    #pragma unroll
    for (int k = 0; k < CPT; k++) {
        int j = tid + k * RT;
        float4 ssj = __ldg(&g_ss[j]);
        float x0 = sdi.x + ssj.x;
        float x1 = sdi.y + ssj.y;
        float x2 = sdi.z + ssj.z;
        float x3 = sdi.w + ssj.w;
        float sa = fabsf(x0) + fabsf(x1);
        float sb = fabsf(x2) + fabsf(x3);
        float sc = ci + adj[j];
        sc = fmaf(0.1f, sa + sb, sc);
        unsigned u = __float_as_uint(sc);
        u ^= ((unsigned)(((int)u) >> 31)) | 0x80000000u;
        key[k] = ((unsigned long long)u << 32) |
                 (unsigned long long)(0xFFFFFFFFu - (unsigned)j);
    }

    // ---- sort 8 keys descending (Batcher, 19 CE) ----
#define CE(a, b) { unsigned long long _x = key[a], _y = key[b]; \
                   key[a] = (_x > _y) ? _x : _y; key[b] = (_x > _y) ? _y : _x; }
    CE(0,1) CE(2,3) CE(0,2) CE(1,3) CE(1,2)
    CE(4,5) CE(6,7) CE(4,6) CE(5,7) CE(5,6)
    CE(0,4) CE(1,5) CE(2,6) CE(3,7)
    CE(2,4) CE(3,5)
    CE(1,2) CE(3,4) CE(5,6)
#undef CE

    // ---- Phase A: per-warp top-15 ----
    unsigned long long mine;
    warp_top15(key, lane, mine);
    if (lane < TOPK) pool[wid * TOPK + lane] = mine;
    __syncthreads();

    // ---- Phase B: warp 0 merges 240 survivors ----
    if (wid == 0) {
        unsigned long long k2[CPT];
        #pragma unroll
        for (int r = 0; r < CPT; r++) {
            int s = lane + r * 32;
            k2[r] = (s < (RT / 32) * TOPK) ? pool[s] : 0ULL;
        }
#define CE(a, b) { unsigned long long _x = k2[a], _y = k2[b]; \
                   k2[a] = (_x > _y) ? _x : _y; k2[b] = (_x > _y) ? _y : _x; }
        CE(0,1) CE(2,3) CE(0,2) CE(1,3) CE(1,2)
        CE(4,5) CE(6,7) CE(4,6) CE(5,7) CE(5,6)
        CE(0,4) CE(1,5) CE(2,6) CE(3,7)
        CE(2,4) CE(3,5)
        CE(1,2) CE(3,4) CE(5,6)
#undef CE
        unsigned long long fin;
        warp_top15(k2, lane, fin);
        if (lane < TOPK) s_sel[lane] = fin;
    }
    __syncthreads();

    // ---- decode + softmax + write ----
    if (tid < TOPK) {
        unsigned long long k64 = s_sel[tid];
        unsigned u = (unsigned)(k64 >> 32);
        float v = (u & 0x80000000u) ? __uint_as_float(u ^ 0x80000000u)
                                    : __uint_as_float(~u);
        unsigned j = 0xFFFFFFFFu - (unsigned)(k64 & 0xFFFFFFFFu);

        unsigned u0 = (unsigned)(s_sel[0] >> 32);
        float v0 = (u0 & 0x80000000u) ? __uint_as_float(u0 ^ 0x80000000u)
                                      : __uint_as_float(~u0);
        s_ex[tid] = expf(v - v0);

        out[(size_t)i * TOPK + tid] = (float)j;
        out[(size_t)NN * TOPK + (size_t)i * TOPK + tid] = (float)i;
    }
    __syncthreads();
    if (tid < TOPK) {
        float sum = 0.f;
        #pragma unroll
        for (int r = 0; r < TOPK; r++) sum += s_ex[r];
        out[2 * (size_t)NN * TOPK + (size_t)i * TOPK + tid] = s_ex[tid] / sum;
    }
}

// ---------------- launcher ----------------
extern "C" void kernel_launch(void* const* d_in, const int* in_sizes, int n_in,
                              void* d_out, int out_size) {
    const float*   emb  = (const float*)d_in[0];
    const float*   W    = (const float*)d_in[1];
    const float*   att  = (const float*)d_in[2];
    const float*   lam  = (const float*)d_in[3];
    const uint8_t* mask = (const uint8_t*)d_in[4];
    const uint8_t* act  = (const uint8_t*)d_in[5];
    const int*     eidx = (const int*)d_in[6];
    const float*   ew   = (const float*)d_in[7];
    float* out = (float*)d_out;

    k_setup<<<21, 256>>>((const unsigned*)mask, W, att);
    k_mid<<<256, 1024>>>(emb, eidx, ew, act);
    k_row<<<NN, RT>>>(mask, act, lam, out);
}

// round 7
// speedup vs baseline: 8.0688x; 1.2766x over previous
#include <cuda_runtime.h>
#include <cstdint>
#include <math.h>

#define NN     4096
#define HDIM   256
#define HEADS  4
#define HD     64
#define EC     131072
#define TOPK   15
#define CAP    160
#define RT     512
#define CPT    8
#define BUFSZ  256
#define FULLM  0xffffffffu

// ---------------- device scratch ----------------
__device__ float2 g_vd[HEADS][HDIM];
__device__ float2 g_vs[HEADS][HDIM];
__device__ float4 g_sd[NN];
__device__ float4 g_ss[NN];
__device__ float  g_badj[NN];            // act_j ? 0.15*sum(ss_j) : -inf
__device__ int    g_cur[NN];
__device__ ulonglong2 g_edge[NN * CAP];  // .x = (pos<<32)|float_bits(w), .y = col
__device__ int    g_is_byte;

// ---------------- double-single helpers ----------------
__device__ __forceinline__ void dsadd(float& s, float& c, float p, float pe) {
    float t = s + p;
    float z = t - s;
    float e = (s - (t - z)) + (p - z);
    s = t;
    c += e + pe;
}

// ---------------- L1: detect bool width + zero counters + fold ----------------
__global__ __launch_bounds__(256) void k_setup(const unsigned* __restrict__ mask_words,
                                               const float* __restrict__ W,
                                               const float* __restrict__ att) {
    int b = blockIdx.x, tid = threadIdx.x;
    if (b == 0) {
        __shared__ int s_byte;
        if (tid == 0) s_byte = 0;
        __syncthreads();
        for (int t = tid; t < 4096; t += 256) {
            unsigned w = mask_words[t];
            if (w > 1u) {
                unsigned b0 = w & 0xFF, b1 = (w >> 8) & 0xFF,
                         b2 = (w >> 16) & 0xFF, b3 = w >> 24;
                if (b0 <= 1u && b1 <= 1u && b2 <= 1u && b3 <= 1u) s_byte = 1;
            }
        }
        __syncthreads();
        if (tid == 0) g_is_byte = s_byte;
    } else if (b <= 16) {
        g_cur[(b - 1) * 256 + tid] = 0;
    } else {
        int h = b - 17;
        int k = tid;
        float sd = 0.f, cd = 0.f, ss = 0.f, cs = 0.f;
        #pragma unroll 8
        for (int dd = 0; dd < HD; dd++) {
            float w   = W[(h * HD + dd) * HDIM + k];
            float ad  = att[h * 2 * HD + dd];
            float as_ = att[h * 2 * HD + HD + dd];
            float p = ad * w;  float pe = fmaf(ad, w, -p);
            dsadd(sd, cd, p, pe);
            p = as_ * w;       pe = fmaf(as_, w, -p);
            dsadd(ss, cs, p, pe);
        }
        float hi = sd + cd;
        g_vd[h][k] = make_float2(hi, (sd - hi) + cd);
        hi = ss + cs;
        g_vs[h][k] = make_float2(hi, (ss - hi) + cs);
    }
}

// ---------------- L2: sds + edge scatter ----------------
__global__ __launch_bounds__(1024) void k_mid(const float* __restrict__ E,
                                              const int* __restrict__ eidx,
                                              const float* __restrict__ ew,
                                              const uint8_t* __restrict__ act) {
    int b = blockIdx.x;
    if (b < 128) {
        int wid = threadIdx.x >> 5;
        int lane = threadIdx.x & 31;
        int g = b * 32 + wid;
        const float* er = E + (size_t)g * HDIM;
        float s[8], c[8];
        #pragma unroll
        for (int a = 0; a < 8; a++) { s[a] = 0.f; c[a] = 0.f; }
        for (int k = lane; k < HDIM; k += 32) {
            float e = er[k];
            #pragma unroll
            for (int h = 0; h < HEADS; h++) {
                float2 v = g_vd[h][k];
                float p = e * v.x;
                float pe = fmaf(e, v.x, -p);
                pe = fmaf(e, v.y, pe);
                dsadd(s[h], c[h], p, pe);
                v = g_vs[h][k];
                p = e * v.x;
                pe = fmaf(e, v.x, -p);
                pe = fmaf(e, v.y, pe);
                dsadd(s[4 + h], c[4 + h], p, pe);
            }
        }
        #pragma unroll
        for (int off = 16; off; off >>= 1) {
            #pragma unroll
            for (int a = 0; a < 8; a++) {
                float os = __shfl_down_sync(FULLM, s[a], off);
                float oc = __shfl_down_sync(FULLM, c[a], off);
                float t = s[a] + os;
                float z = t - s[a];
                c[a] += oc + ((s[a] - (t - z)) + (os - z));
                s[a] = t;
            }
        }
        if (lane == 0) {
            g_sd[g] = make_float4(s[0] + c[0], s[1] + c[1], s[2] + c[2], s[3] + c[3]);
            float t0 = s[4] + c[4], t1 = s[5] + c[5], t2 = s[6] + c[6], t3 = s[7] + c[7];
            g_ss[g] = make_float4(t0, t1, t2, t3);
            bool aj = g_is_byte ? (act[g] != 0) : (((const unsigned*)act)[g] != 0u);
            g_badj[g] = aj ? 0.15f * ((t0 + t1) + (t2 + t3)) : -INFINITY;
        }
    } else {
        int e = (b - 128) * 1024 + threadIdx.x;
        if (e < EC) {
            int r = eidx[e];
            int cc = eidx[EC + e];
            int p = atomicAdd(&g_cur[r], 1);
            if (p < CAP) {
                ulonglong2 rec;
                rec.x = ((unsigned long long)(unsigned)e << 32) |
                        (unsigned long long)__float_as_uint(ew[e]);
                rec.y = (unsigned long long)(unsigned)cc;
                g_edge[r * CAP + p] = rec;
            }
        }
    }
}

// warp0-only: largest bin B with suffix-count(B) >= K; outAbove = count in bins > B
__device__ __forceinline__ void scan_hist(const int* __restrict__ hist, int K,
                                          int* outB, int* outAbove) {
    int lane = threadIdx.x & 31;
    int base = lane * 8;
    int h[8];
    #pragma unroll
    for (int r = 0; r < 8; r++) h[r] = hist[base + r];
    int ls[8];
    int s = 0;
    #pragma unroll
    for (int r = 7; r >= 0; r--) { s += h[r]; ls[r] = s; }
    int run = s;
    #pragma unroll
    for (int off = 1; off < 32; off <<= 1) {
        int t = __shfl_down_sync(FULLM, run, off);
        if (lane + off < 32) run += t;
    }
    int above = run - s;   // keys in lanes > me (higher bins)
    int cand = -1, candAbove = 0;
    #pragma unroll
    for (int r = 7; r >= 0; r--) {
        if (cand < 0 && above + ls[r] >= K) {
            cand = base + r;
            candAbove = above + ls[r] - h[r];
        }
    }
    int bestB = cand, bestA = candAbove;
    #pragma unroll
    for (int off = 16; off; off >>= 1) {
        int ob = __shfl_xor_sync(FULLM, bestB, off);
        int oa = __shfl_xor_sync(FULLM, bestA, off);
        if (ob > bestB) { bestB = ob; bestA = oa; }
    }
    if (lane == 0) {
        *outB = (bestB < 0) ? 0 : bestB;
        *outAbove = (bestB < 0) ? 0 : bestA;
    }
}

// compute 8 candidate u32 keys for row i (BYTE selects mask element width)
template<bool BYTE>
__device__ __forceinline__ void compute_keys(unsigned kk[CPT], int tid,
                                             const float4 sdi, float ci, float lam,
                                             bool acti,
                                             const uint8_t* __restrict__ mrow8,
                                             const unsigned* __restrict__ mrow32,
                                             const unsigned long long* __restrict__ corr) {
    #pragma unroll
    for (int k = 0; k < CPT; k++) {
        int j = tid + k * RT;
        float4 ssj = __ldg(&g_ss[j]);
        float x0 = sdi.x + ssj.x;
        float x1 = sdi.y + ssj.y;
        float x2 = sdi.z + ssj.z;
        float x3 = sdi.w + ssj.w;
        float sa = fabsf(x0) + fabsf(x1);
        float sb = fabsf(x2) + fabsf(x3);
        float w = __uint_as_float((unsigned)(((const unsigned*)corr)[2 * j]));  // low word
        float a = g_badj[j];
        bool mj = BYTE ? (mrow8[j] != 0) : (mrow32[j] != 0u);
        float sc = ci + fmaf(lam, w, a);
        sc = fmaf(0.1f, sa + sb, sc);
        sc = (acti && mj) ? sc : -INFINITY;
        unsigned u = __float_as_uint(sc);
        u ^= ((unsigned)(((int)u) >> 31)) | 0x80000000u;
        kk[k] = u;
    }
}

// ---------------- L3: one row per block ----------------
__global__ __launch_bounds__(RT, 2) void k_row(const uint8_t* __restrict__ mask,
                                               const uint8_t* __restrict__ act,
                                               const float* __restrict__ lambda_p,
                                               float* __restrict__ out) {
    __shared__ unsigned long long corr[NN];    // 32 KB
    __shared__ int hist1[256];
    __shared__ int hist2[256];
    __shared__ unsigned long long buf[BUFSZ];
    __shared__ unsigned long long s_sel[TOPK];
    __shared__ float s_ex[TOPK];
    __shared__ int s_cnt, s_B1, s_above1, s_B2, s_above2;

    const int i = blockIdx.x;
    const int tid = threadIdx.x;
    const int lane = tid & 31;
    const int wid = tid >> 5;

    // ---- phase 1: zero everything ----
    #pragma unroll
    for (int k = 0; k < NN / RT; k++) corr[tid + k * RT] = 0ULL;
    if (tid < 256) { hist1[tid] = 0; hist2[tid] = 0; }
    else if (tid < 256 + TOPK) s_sel[tid - 256] = 0ULL;
    if (tid == RT - 1) s_cnt = 0;
    __syncthreads();

    // ---- phase 2: scatter row edges (last-write-wins via max edge position) ----
    int cnt = g_cur[i];
    if (cnt > CAP) cnt = CAP;
    if (tid < cnt) {
        ulonglong2 rec = g_edge[i * CAP + tid];
        atomicMax(&corr[(int)rec.y], rec.x);
    }
    __syncthreads();

    const float4 sdi = g_sd[i];
    const float ci = 0.15f * ((sdi.x + sdi.y) + (sdi.z + sdi.w));
    const float lam = __ldg(lambda_p);
    const int is_byte = g_is_byte;
    const uint8_t*  mrow8  = mask + (size_t)i * NN;
    const unsigned* mrow32 = (const unsigned*)mask + (size_t)i * NN;
    const bool acti = is_byte ? (act[i] != 0) : (((const unsigned*)act)[i] != 0u);

    // ---- phase 3: compute 8 keys + level-1 histogram (warp-aggregated) ----
    unsigned kk[CPT];
    if (is_byte) compute_keys<true>(kk, tid, sdi, ci, lam, acti, mrow8, mrow32, corr);
    else         compute_keys<false>(kk, tid, sdi, ci, lam, acti, mrow8, mrow32, corr);

    #pragma unroll
    for (int k = 0; k < CPT; k++) {
        unsigned b1 = kk[k] >> 24;
        unsigned peers = __match_any_sync(FULLM, b1);
        if ((peers & ((1u << lane) - 1u)) == 0)      // lowest-lane leader
            atomicAdd(&hist1[b1], (int)__popc(peers));
    }
    __syncthreads();

    // ---- phase 4: level-1 scan ----
    if (wid == 0) scan_hist(hist1, TOPK, &s_B1, &s_above1);
    __syncthreads();
    const int B1 = s_B1;
    const int above1 = s_above1;

    // ---- phase 5: level-2 histogram within bin B1 ----
    #pragma unroll
    for (int k = 0; k < CPT; k++) {
        if ((int)(kk[k] >> 24) == B1)
            atomicAdd(&hist2[(kk[k] >> 16) & 0xFF], 1);
    }
    __syncthreads();

    // ---- phase 6: level-2 scan (need r = 15 - above1 more from bin B1) ----
    if (wid == 0) scan_hist(hist2, TOPK - above1, &s_B2, &s_above2);
    __syncthreads();
    const int B2 = s_B2;

    // ---- phase 7: append candidates ----
    #pragma unroll
    for (int k = 0; k < CPT; k++) {
        int b1k = (int)(kk[k] >> 24);
        bool cand = (b1k > B1) || (b1k == B1 && (int)((kk[k] >> 16) & 0xFF) >= B2);
        if (cand) {
            int p = atomicAdd(&s_cnt, 1);
            if (p < BUFSZ) {
                int j = tid + k * RT;
                buf[p] = ((unsigned long long)kk[k] << 32) |
                         (unsigned long long)(0xFFFFFFFFu - (unsigned)j);
            }
        }
    }
    __syncthreads();

    // ---- phase 8: rank-select top-15 from <=BUFSZ candidates ----
    int n = s_cnt < BUFSZ ? s_cnt : BUFSZ;
    if (tid < BUFSZ) {
        unsigned long long K = (tid < n) ? buf[tid] : 0ULL;
        int rank = 0;
        for (int s = 0; s < n; s++) rank += (buf[s] > K);
        if (tid < n && rank < TOPK) s_sel[rank] = K;
    }
    __syncthreads();

    // ---- phase 9: decode + softmax + write ----
    if (tid < TOPK) {
        unsigned long long k64 = s_sel[tid];
        unsigned u = (unsigned)(k64 >> 32);
        float v = (u & 0x80000000u) ? __uint_as_float(u ^ 0x80000000u)
                                    : __uint_as_float(~u);
        unsigned j = 0xFFFFFFFFu - (unsigned)(k64 & 0xFFFFFFFFu);

        unsigned u0 = (unsigned)(s_sel[0] >> 32);
        float v0 = (u0 & 0x80000000u) ? __uint_as_float(u0 ^ 0x80000000u)
                                      : __uint_as_float(~u0);
        s_ex[tid] = expf(v - v0);

        out[(size_t)i * TOPK + tid] = (float)j;
        out[(size_t)NN * TOPK + (size_t)i * TOPK + tid] = (float)i;
    }
    __syncthreads();
    if (tid < TOPK) {
        float sum = 0.f;
        #pragma unroll
        for (int r = 0; r < TOPK; r++) sum += s_ex[r];
        out[2 * (size_t)NN * TOPK + (size_t)i * TOPK + tid] = s_ex[tid] / sum;
    }
}

// ---------------- launcher ----------------
extern "C" void kernel_launch(void* const* d_in, const int* in_sizes, int n_in,
                              void* d_out, int out_size) {
    const float*   emb  = (const float*)d_in[0];
    const float*   W    = (const float*)d_in[1];
    const float*   att  = (const float*)d_in[2];
    const float*   lam  = (const float*)d_in[3];
    const uint8_t* mask = (const uint8_t*)d_in[4];
    const uint8_t* act  = (const uint8_t*)d_in[5];
    const int*     eidx = (const int*)d_in[6];
    const float*   ew   = (const float*)d_in[7];
    float* out = (float*)d_out;

    k_setup<<<21, 256>>>((const unsigned*)mask, W, att);
    k_mid<<<256, 1024>>>(emb, eidx, ew, act);
    k_row<<<NN, RT>>>(mask, act, lam, out);
}